// round 1
// baseline (speedup 1.0000x reference)
#include <cuda_runtime.h>

#define NGRAPH 128
#define MDIM 512
#define NDIM 512
#define DDIM 512
#define MP1 513

// ---------------- scratch (static device globals: allocation-free) ----------------
__device__ float g_K[(size_t)NGRAPH * MDIM * NDIM];     // exp(-affinity/lambda), 134 MB
__device__ float g_inv_tra[NGRAPH * MDIM];
__device__ float g_inv_det[NGRAPH * NDIM];
__device__ float g_F[NGRAPH * MP1];
__device__ float g_G[NGRAPH * MP1];

__device__ __forceinline__ float warp_sum(float v) {
    v += __shfl_xor_sync(0xffffffffu, v, 16);
    v += __shfl_xor_sync(0xffffffffu, v, 8);
    v += __shfl_xor_sync(0xffffffffu, v, 4);
    v += __shfl_xor_sync(0xffffffffu, v, 2);
    v += __shfl_xor_sync(0xffffffffu, v, 1);
    return v;
}

// ---------------- 1) inverse row norms ----------------
// grid (8192, 2), block 256. blockIdx.y==0 -> tra, ==1 -> det. One warp per row.
__global__ void norm_kernel(const float* __restrict__ tra, const float* __restrict__ det) {
    int which = blockIdx.y;
    const float* src = (which == 0) ? tra : det;
    float* dst = (which == 0) ? g_inv_tra : g_inv_det;
    int warp = threadIdx.x >> 5, lane = threadIdx.x & 31;
    int row = blockIdx.x * 8 + warp;           // 0 .. 65535
    const float* p = src + (size_t)row * DDIM;
    float s = 0.f;
#pragma unroll
    for (int c = 0; c < 4; c++) {
        float4 v = *(const float4*)&p[(lane + c * 32) * 4];
        s += v.x * v.x + v.y * v.y + v.z * v.z + v.w * v.w;
    }
    s = warp_sum(s);
    if (lane == 0) dst[row] = rsqrtf(s);
}

// ---------------- 2) GEMM  C[m][n] = sum_d tra[g][m][d]*det[g][n][d]; K = exp(-aff/lam) ----------------
// 128x128 tile, BK=8, 256 threads, 8x8 micro, double buffered.
__global__ __launch_bounds__(256, 2) void gemm_kernel(
    const float* __restrict__ det, const float* __restrict__ tra,
    const float* __restrict__ alpha_p, const float* __restrict__ eps_p)
{
    __shared__ __align__(16) float As[2][8][128];
    __shared__ __align__(16) float Bs[2][8][128];
    int g = blockIdx.z;
    int m0 = blockIdx.y * 128, n0 = blockIdx.x * 128;
    const float* A  = tra + (size_t)g * MDIM * DDIM;   // [m][d]
    const float* Bp = det + (size_t)g * NDIM * DDIM;   // [n][d]
    int tid = threadIdx.x;
    int lr = tid >> 1;            // 0..127
    int lc = (tid & 1) * 4;       // 0 or 4
    int ty = tid >> 4, tx = tid & 15;

    float acc[8][8];
#pragma unroll
    for (int i = 0; i < 8; i++)
#pragma unroll
        for (int j = 0; j < 8; j++) acc[i][j] = 0.f;

    // prologue: tile k0=0 -> buffer 0
    {
        float4 a4 = *(const float4*)&A[(size_t)(m0 + lr) * DDIM + lc];
        float4 b4 = *(const float4*)&Bp[(size_t)(n0 + lr) * DDIM + lc];
        As[0][lc + 0][lr] = a4.x; As[0][lc + 1][lr] = a4.y; As[0][lc + 2][lr] = a4.z; As[0][lc + 3][lr] = a4.w;
        Bs[0][lc + 0][lr] = b4.x; Bs[0][lc + 1][lr] = b4.y; Bs[0][lc + 2][lr] = b4.z; Bs[0][lc + 3][lr] = b4.w;
    }
    __syncthreads();

    int buf = 0;
    for (int k0 = 0; k0 < DDIM; k0 += 8) {
        bool nxt = (k0 + 8) < DDIM;
        if (nxt) {
            float4 a4 = *(const float4*)&A[(size_t)(m0 + lr) * DDIM + k0 + 8 + lc];
            float4 b4 = *(const float4*)&Bp[(size_t)(n0 + lr) * DDIM + k0 + 8 + lc];
            int nb = buf ^ 1;  // safe: readers of nb finished before last sync
            As[nb][lc + 0][lr] = a4.x; As[nb][lc + 1][lr] = a4.y; As[nb][lc + 2][lr] = a4.z; As[nb][lc + 3][lr] = a4.w;
            Bs[nb][lc + 0][lr] = b4.x; Bs[nb][lc + 1][lr] = b4.y; Bs[nb][lc + 2][lr] = b4.z; Bs[nb][lc + 3][lr] = b4.w;
        }
#pragma unroll
        for (int kk = 0; kk < 8; kk++) {
            float ar[8], br[8];
            *(float4*)(ar)     = *(const float4*)&As[buf][kk][ty * 8];
            *(float4*)(ar + 4) = *(const float4*)&As[buf][kk][ty * 8 + 4];
            *(float4*)(br)     = *(const float4*)&Bs[buf][kk][tx * 8];
            *(float4*)(br + 4) = *(const float4*)&Bs[buf][kk][tx * 8 + 4];
#pragma unroll
            for (int i = 0; i < 8; i++)
#pragma unroll
                for (int j = 0; j < 8; j++) acc[i][j] += ar[i] * br[j];
        }
        __syncthreads();
        buf ^= 1;
    }

    // epilogue: K = exp(-aff/lam)
    float lam = __expf(eps_p[0]) + 0.03f;
    float neg_inv_lam = -1.0f / lam;
    float invA[8], invB[8];
#pragma unroll
    for (int i = 0; i < 8; i++) invA[i] = g_inv_tra[g * MDIM + m0 + ty * 8 + i];
#pragma unroll
    for (int j = 0; j < 8; j++) invB[j] = g_inv_det[g * NDIM + n0 + tx * 8 + j];
    float* Kg = g_K + (size_t)g * MDIM * NDIM;
#pragma unroll
    for (int i = 0; i < 8; i++) {
        int row = m0 + ty * 8 + i;
        float o[8];
#pragma unroll
        for (int j = 0; j < 8; j++) {
            float aff = acc[i][j] * invA[i] * invB[j];
            o[j] = __expf(aff * neg_inv_lam);
        }
        *(float4*)&Kg[(size_t)row * NDIM + n0 + tx * 8]     = *(float4*)(o);
        *(float4*)&Kg[(size_t)row * NDIM + n0 + tx * 8 + 4] = *(float4*)(o + 4);
    }
}

// ---------------- 3) Sinkhorn iterations (one CTA per graph, 512 threads) ----------------
// Primal form: G_j = b_j / (sum_i K_ij F_i + kappa*F_M);  F_i = a_i / (sum_j K_ij G_j + kappa*G_N)
// Bin scalars: F_M = 0.5/(kappa*sumG_all);  G_N = 0.5/(kappa*(sumF + F_M)).
__global__ __launch_bounds__(512, 1) void sinkhorn_kernel(
    const float* __restrict__ alpha_p, const float* __restrict__ eps_p)
{
    __shared__ __align__(16) float sF[520];
    __shared__ __align__(16) float sG[520];
    __shared__ __align__(16) float sSpart[4][512];
    __shared__ __align__(16) float sRed[2][4][16];
    __shared__ __align__(16) float sWred[16];

    int g = blockIdx.x;
    const float* Kg = g_K + (size_t)g * MDIM * NDIM;
    int t = threadIdx.x;
    int u = t & 127;          // column group: owns cols 4u..4u+3
    int rq = t >> 7;          // row residue 0..3
    int warp = t >> 5, lane = t & 31;

    float lam = __expf(eps_p[0]) + 0.03f;
    float kappa = __expf(-alpha_p[0] / lam);
    const float AB = 1.0f / 1024.0f;   // a_i = b_j = 1/(M+N)
    const float AB_LAST = 0.5f;        // a_M = b_N = 512/1024

    // ---- pass 0: column sums with F^0 = 1 -> G^1
    {
        float4 S4 = make_float4(0.f, 0.f, 0.f, 0.f);
        for (int i0 = 0; i0 < MDIM; i0 += 16) {
#pragma unroll
            for (int k = 0; k < 4; k++) {
                int row = i0 + k * 4 + rq;
                float4 v = *(const float4*)&Kg[(size_t)row * NDIM + 4 * u];
                S4.x += v.x; S4.y += v.y; S4.z += v.z; S4.w += v.w;
            }
        }
        *(float4*)&sSpart[rq][4 * u] = S4;
    }
    __syncthreads();
    float newG0;
    {
        float Sj = sSpart[0][t] + sSpart[1][t] + sSpart[2][t] + sSpart[3][t];
        newG0 = AB / (Sj + kappa);   // F^0_M = 1
        sG[t] = newG0;
    }
    float G_N = AB_LAST / (kappa * 513.0f);
    __syncthreads();
    float sumG_all;
    {
        float v = warp_sum(newG0);
        if (lane == 0) sWred[warp] = v;
        __syncthreads();
        float s = 0.f;
#pragma unroll
        for (int w = 0; w < 16; w++) s += sWred[w];
        sumG_all = s + G_N;
    }
    __syncthreads();

    float F_M = 1.0f;

    // ---- passes 1..8: fused F-update(t) + column sums for G-update(t+1)
    for (int pass = 1; pass <= 8; pass++) {
        F_M = AB_LAST / (kappa * sumG_all);
        float4 G4 = *(const float4*)&sG[4 * u];
        float kGN = kappa * G_N;
        float4 S4 = make_float4(0.f, 0.f, 0.f, 0.f);
        const bool last = (pass == 8);
        int it = 0;
        for (int i0 = 0; i0 < MDIM; i0 += 16) {
            float4 v0 = *(const float4*)&Kg[(size_t)(i0 + 0  + rq) * NDIM + 4 * u];
            float4 v1 = *(const float4*)&Kg[(size_t)(i0 + 4  + rq) * NDIM + 4 * u];
            float4 v2 = *(const float4*)&Kg[(size_t)(i0 + 8  + rq) * NDIM + 4 * u];
            float4 v3 = *(const float4*)&Kg[(size_t)(i0 + 12 + rq) * NDIM + 4 * u];
            float t0 = v0.x * G4.x + v0.y * G4.y + v0.z * G4.z + v0.w * G4.w;
            float t1 = v1.x * G4.x + v1.y * G4.y + v1.z * G4.z + v1.w * G4.w;
            float t2 = v2.x * G4.x + v2.y * G4.y + v2.z * G4.z + v2.w * G4.w;
            float t3 = v3.x * G4.x + v3.y * G4.y + v3.z * G4.z + v3.w * G4.w;
            t0 = warp_sum(t0); t1 = warp_sum(t1); t2 = warp_sum(t2); t3 = warp_sum(t3);
            if (lane == 0) {
                sRed[it][0][warp] = t0; sRed[it][1][warp] = t1;
                sRed[it][2][warp] = t2; sRed[it][3][warp] = t3;
            }
            __syncthreads();
            float4 r0v = *(const float4*)&sRed[it][0][4 * rq];
            float4 r1v = *(const float4*)&sRed[it][1][4 * rq];
            float4 r2v = *(const float4*)&sRed[it][2][4 * rq];
            float4 r3v = *(const float4*)&sRed[it][3][4 * rq];
            float Fi0 = __fdividef(AB, r0v.x + r0v.y + r0v.z + r0v.w + kGN);
            float Fi1 = __fdividef(AB, r1v.x + r1v.y + r1v.z + r1v.w + kGN);
            float Fi2 = __fdividef(AB, r2v.x + r2v.y + r2v.z + r2v.w + kGN);
            float Fi3 = __fdividef(AB, r3v.x + r3v.y + r3v.z + r3v.w + kGN);
            if (u == 0) {
                sF[i0 + 0  + rq] = Fi0; sF[i0 + 4  + rq] = Fi1;
                sF[i0 + 8  + rq] = Fi2; sF[i0 + 12 + rq] = Fi3;
            }
            if (!last) {
                S4.x += v0.x * Fi0 + v1.x * Fi1 + v2.x * Fi2 + v3.x * Fi3;
                S4.y += v0.y * Fi0 + v1.y * Fi1 + v2.y * Fi2 + v3.y * Fi3;
                S4.z += v0.z * Fi0 + v1.z * Fi1 + v2.z * Fi2 + v3.z * Fi3;
                S4.w += v0.w * Fi0 + v1.w * Fi1 + v2.w * Fi2 + v3.w * Fi3;
            }
            it ^= 1;
        }
        __syncthreads();
        if (!last) {
            *(float4*)&sSpart[rq][4 * u] = S4;
            __syncthreads();
            float Sj = sSpart[0][t] + sSpart[1][t] + sSpart[2][t] + sSpart[3][t];
            float newG = AB / (Sj + kappa * F_M);
            sG[t] = newG;
            // sumF
            float fv = warp_sum(sF[t]);
            if (lane == 0) sWred[warp] = fv;
            __syncthreads();
            float sumF = 0.f;
#pragma unroll
            for (int w = 0; w < 16; w++) sumF += sWred[w];
            G_N = AB_LAST / (kappa * (sumF + F_M));
            __syncthreads();
            // sumG
            float gv = warp_sum(newG);
            if (lane == 0) sWred[warp] = gv;
            __syncthreads();
            float sg = 0.f;
#pragma unroll
            for (int w = 0; w < 16; w++) sg += sWred[w];
            sumG_all = sg + G_N;
            __syncthreads();
        }
    }

    // store potentials (F^8, G^8 incl. bins)
    g_F[g * MP1 + t] = sF[t];
    g_G[g * MP1 + t] = sG[t];
    if (t == 0) { g_F[g * MP1 + 512] = F_M; g_G[g * MP1 + 512] = G_N; }
}

// ---------------- 4) output: pred[g][i][j] = F_i * K_ij * G_j (bins via kappa) ----------------
// grid (513, 128), block 512; one row per block -> fully coalesced reads/writes.
__global__ void output_kernel(const float* __restrict__ alpha_p, const float* __restrict__ eps_p,
                              float* __restrict__ out)
{
    int g = blockIdx.y;
    int i = blockIdx.x;             // 0..512
    int t = threadIdx.x;            // 0..511
    float lam = __expf(eps_p[0]) + 0.03f;
    float kappa = __expf(-alpha_p[0] / lam);
    float Fi = g_F[g * MP1 + i];
    float GN = g_G[g * MP1 + 512];
    float Gj = g_G[g * MP1 + t];
    float* orow = out + (size_t)g * MP1 * MP1 + (size_t)i * MP1;
    if (i < MDIM) {
        const float* Krow = g_K + (size_t)g * MDIM * NDIM + (size_t)i * NDIM;
        orow[t] = Fi * Krow[t] * Gj;
        if (t == 0) orow[512] = Fi * kappa * GN;
    } else {
        orow[t] = Fi * kappa * Gj;          // Fi == F_M here
        if (t == 0) orow[512] = Fi * kappa * GN;
    }
}

// ---------------- launch ----------------
extern "C" void kernel_launch(void* const* d_in, const int* in_sizes, int n_in,
                              void* d_out, int out_size) {
    const float* det   = (const float*)d_in[0];   // [G, N, D]
    const float* tra   = (const float*)d_in[1];   // [G, M, D]
    const float* alpha = (const float*)d_in[2];   // [1]
    const float* eps   = (const float*)d_in[3];   // [1]
    float* out = (float*)d_out;                   // [G, M+1, N+1]

    norm_kernel<<<dim3(8192, 2), 256>>>(tra, det);
    gemm_kernel<<<dim3(4, 4, 128), 256>>>(det, tra, alpha, eps);
    sinkhorn_kernel<<<128, 512>>>(alpha, eps);
    output_kernel<<<dim3(513, 128), 512>>>(alpha, eps, out);
}

// round 2
// speedup vs baseline: 1.0015x; 1.0015x over previous
#include <cuda_runtime.h>

#define NGRAPH 128
#define MDIM 512
#define NDIM 512
#define DDIM 512
#define MP1 513

// ---------------- scratch (static device globals: allocation-free) ----------------
__device__ float g_K[(size_t)NGRAPH * MDIM * NDIM];     // exp(-affinity/lambda), 134 MB
__device__ float g_inv_tra[NGRAPH * MDIM];
__device__ float g_inv_det[NGRAPH * NDIM];
__device__ float g_F[NGRAPH * MP1];
__device__ float g_G[NGRAPH * MP1];

__device__ __forceinline__ float warp_sum(float v) {
    v += __shfl_xor_sync(0xffffffffu, v, 16);
    v += __shfl_xor_sync(0xffffffffu, v, 8);
    v += __shfl_xor_sync(0xffffffffu, v, 4);
    v += __shfl_xor_sync(0xffffffffu, v, 2);
    v += __shfl_xor_sync(0xffffffffu, v, 1);
    return v;
}

// ---------------- 1) inverse row norms ----------------
// grid (8192, 2), block 256. blockIdx.y==0 -> tra, ==1 -> det. One warp per row.
__global__ void norm_kernel(const float* __restrict__ tra, const float* __restrict__ det) {
    int which = blockIdx.y;
    const float* src = (which == 0) ? tra : det;
    float* dst = (which == 0) ? g_inv_tra : g_inv_det;
    int warp = threadIdx.x >> 5, lane = threadIdx.x & 31;
    int row = blockIdx.x * 8 + warp;           // 0 .. 65535
    const float* p = src + (size_t)row * DDIM;
    float s = 0.f;
#pragma unroll
    for (int c = 0; c < 4; c++) {
        float4 v = *(const float4*)&p[(lane + c * 32) * 4];
        s += v.x * v.x + v.y * v.y + v.z * v.z + v.w * v.w;
    }
    s = warp_sum(s);
    if (lane == 0) dst[row] = rsqrtf(s);
}

// ---------------- 2) GEMM  C[m][n] = sum_d tra[g][m][d]*det[g][n][d]; K = exp(-aff/lam) ----------------
// 128x128 tile, BK=8, 256 threads, 8x8 micro, double buffered.
__global__ __launch_bounds__(256, 2) void gemm_kernel(
    const float* __restrict__ det, const float* __restrict__ tra,
    const float* __restrict__ alpha_p, const float* __restrict__ eps_p)
{
    __shared__ __align__(16) float As[2][8][128];
    __shared__ __align__(16) float Bs[2][8][128];
    int g = blockIdx.z;
    int m0 = blockIdx.y * 128, n0 = blockIdx.x * 128;
    const float* A  = tra + (size_t)g * MDIM * DDIM;   // [m][d]
    const float* Bp = det + (size_t)g * NDIM * DDIM;   // [n][d]
    int tid = threadIdx.x;
    int lr = tid >> 1;            // 0..127
    int lc = (tid & 1) * 4;       // 0 or 4
    int ty = tid >> 4, tx = tid & 15;

    float acc[8][8];
#pragma unroll
    for (int i = 0; i < 8; i++)
#pragma unroll
        for (int j = 0; j < 8; j++) acc[i][j] = 0.f;

    // prologue: tile k0=0 -> buffer 0
    {
        float4 a4 = *(const float4*)&A[(size_t)(m0 + lr) * DDIM + lc];
        float4 b4 = *(const float4*)&Bp[(size_t)(n0 + lr) * DDIM + lc];
        As[0][lc + 0][lr] = a4.x; As[0][lc + 1][lr] = a4.y; As[0][lc + 2][lr] = a4.z; As[0][lc + 3][lr] = a4.w;
        Bs[0][lc + 0][lr] = b4.x; Bs[0][lc + 1][lr] = b4.y; Bs[0][lc + 2][lr] = b4.z; Bs[0][lc + 3][lr] = b4.w;
    }
    __syncthreads();

    int buf = 0;
    for (int k0 = 0; k0 < DDIM; k0 += 8) {
        bool nxt = (k0 + 8) < DDIM;
        if (nxt) {
            float4 a4 = *(const float4*)&A[(size_t)(m0 + lr) * DDIM + k0 + 8 + lc];
            float4 b4 = *(const float4*)&Bp[(size_t)(n0 + lr) * DDIM + k0 + 8 + lc];
            int nb = buf ^ 1;  // safe: readers of nb finished before last sync
            As[nb][lc + 0][lr] = a4.x; As[nb][lc + 1][lr] = a4.y; As[nb][lc + 2][lr] = a4.z; As[nb][lc + 3][lr] = a4.w;
            Bs[nb][lc + 0][lr] = b4.x; Bs[nb][lc + 1][lr] = b4.y; Bs[nb][lc + 2][lr] = b4.z; Bs[nb][lc + 3][lr] = b4.w;
        }
#pragma unroll
        for (int kk = 0; kk < 8; kk++) {
            float ar[8], br[8];
            *(float4*)(ar)     = *(const float4*)&As[buf][kk][ty * 8];
            *(float4*)(ar + 4) = *(const float4*)&As[buf][kk][ty * 8 + 4];
            *(float4*)(br)     = *(const float4*)&Bs[buf][kk][tx * 8];
            *(float4*)(br + 4) = *(const float4*)&Bs[buf][kk][tx * 8 + 4];
#pragma unroll
            for (int i = 0; i < 8; i++)
#pragma unroll
                for (int j = 0; j < 8; j++) acc[i][j] += ar[i] * br[j];
        }
        __syncthreads();
        buf ^= 1;
    }

    // epilogue: K = exp(-aff/lam)
    float lam = __expf(eps_p[0]) + 0.03f;
    float neg_inv_lam = -1.0f / lam;
    float invA[8], invB[8];
#pragma unroll
    for (int i = 0; i < 8; i++) invA[i] = g_inv_tra[g * MDIM + m0 + ty * 8 + i];
#pragma unroll
    for (int j = 0; j < 8; j++) invB[j] = g_inv_det[g * NDIM + n0 + tx * 8 + j];
    float* Kg = g_K + (size_t)g * MDIM * NDIM;
#pragma unroll
    for (int i = 0; i < 8; i++) {
        int row = m0 + ty * 8 + i;
        float o[8];
#pragma unroll
        for (int j = 0; j < 8; j++) {
            float aff = acc[i][j] * invA[i] * invB[j];
            o[j] = __expf(aff * neg_inv_lam);
        }
        *(float4*)&Kg[(size_t)row * NDIM + n0 + tx * 8]     = *(float4*)(o);
        *(float4*)&Kg[(size_t)row * NDIM + n0 + tx * 8 + 4] = *(float4*)(o + 4);
    }
}

// ---------------- 3) Sinkhorn iterations (one CTA per graph, 512 threads) ----------------
// Primal form: G_j = b_j / (sum_i K_ij F_i + kappa*F_M);  F_i = a_i / (sum_j K_ij G_j + kappa*G_N)
// Bin scalars: F_M = 0.5/(kappa*sumG_all);  G_N = 0.5/(kappa*(sumF + F_M)).
__global__ __launch_bounds__(512, 1) void sinkhorn_kernel(
    const float* __restrict__ alpha_p, const float* __restrict__ eps_p)
{
    __shared__ __align__(16) float sF[520];
    __shared__ __align__(16) float sG[520];
    __shared__ __align__(16) float sSpart[4][512];
    __shared__ __align__(16) float sRed[2][4][16];
    __shared__ __align__(16) float sWred[16];

    int g = blockIdx.x;
    const float* Kg = g_K + (size_t)g * MDIM * NDIM;
    int t = threadIdx.x;
    int u = t & 127;          // column group: owns cols 4u..4u+3
    int rq = t >> 7;          // row residue 0..3
    int warp = t >> 5, lane = t & 31;

    float lam = __expf(eps_p[0]) + 0.03f;
    float kappa = __expf(-alpha_p[0] / lam);
    const float AB = 1.0f / 1024.0f;   // a_i = b_j = 1/(M+N)
    const float AB_LAST = 0.5f;        // a_M = b_N = 512/1024

    // ---- pass 0: column sums with F^0 = 1 -> G^1
    {
        float4 S4 = make_float4(0.f, 0.f, 0.f, 0.f);
        for (int i0 = 0; i0 < MDIM; i0 += 16) {
#pragma unroll
            for (int k = 0; k < 4; k++) {
                int row = i0 + k * 4 + rq;
                float4 v = *(const float4*)&Kg[(size_t)row * NDIM + 4 * u];
                S4.x += v.x; S4.y += v.y; S4.z += v.z; S4.w += v.w;
            }
        }
        *(float4*)&sSpart[rq][4 * u] = S4;
    }
    __syncthreads();
    float newG0;
    {
        float Sj = sSpart[0][t] + sSpart[1][t] + sSpart[2][t] + sSpart[3][t];
        newG0 = AB / (Sj + kappa);   // F^0_M = 1
        sG[t] = newG0;
    }
    float G_N = AB_LAST / (kappa * 513.0f);
    __syncthreads();
    float sumG_all;
    {
        float v = warp_sum(newG0);
        if (lane == 0) sWred[warp] = v;
        __syncthreads();
        float s = 0.f;
#pragma unroll
        for (int w = 0; w < 16; w++) s += sWred[w];
        sumG_all = s + G_N;
    }
    __syncthreads();

    float F_M = 1.0f;

    // ---- passes 1..8: fused F-update(t) + column sums for G-update(t+1)
    for (int pass = 1; pass <= 8; pass++) {
        F_M = AB_LAST / (kappa * sumG_all);
        float4 G4 = *(const float4*)&sG[4 * u];
        float kGN = kappa * G_N;
        float4 S4 = make_float4(0.f, 0.f, 0.f, 0.f);
        const bool last = (pass == 8);
        int it = 0;
        for (int i0 = 0; i0 < MDIM; i0 += 16) {
            float4 v0 = *(const float4*)&Kg[(size_t)(i0 + 0  + rq) * NDIM + 4 * u];
            float4 v1 = *(const float4*)&Kg[(size_t)(i0 + 4  + rq) * NDIM + 4 * u];
            float4 v2 = *(const float4*)&Kg[(size_t)(i0 + 8  + rq) * NDIM + 4 * u];
            float4 v3 = *(const float4*)&Kg[(size_t)(i0 + 12 + rq) * NDIM + 4 * u];
            float t0 = v0.x * G4.x + v0.y * G4.y + v0.z * G4.z + v0.w * G4.w;
            float t1 = v1.x * G4.x + v1.y * G4.y + v1.z * G4.z + v1.w * G4.w;
            float t2 = v2.x * G4.x + v2.y * G4.y + v2.z * G4.z + v2.w * G4.w;
            float t3 = v3.x * G4.x + v3.y * G4.y + v3.z * G4.z + v3.w * G4.w;
            t0 = warp_sum(t0); t1 = warp_sum(t1); t2 = warp_sum(t2); t3 = warp_sum(t3);
            if (lane == 0) {
                sRed[it][0][warp] = t0; sRed[it][1][warp] = t1;
                sRed[it][2][warp] = t2; sRed[it][3][warp] = t3;
            }
            __syncthreads();
            float4 r0v = *(const float4*)&sRed[it][0][4 * rq];
            float4 r1v = *(const float4*)&sRed[it][1][4 * rq];
            float4 r2v = *(const float4*)&sRed[it][2][4 * rq];
            float4 r3v = *(const float4*)&sRed[it][3][4 * rq];
            float Fi0 = __fdividef(AB, r0v.x + r0v.y + r0v.z + r0v.w + kGN);
            float Fi1 = __fdividef(AB, r1v.x + r1v.y + r1v.z + r1v.w + kGN);
            float Fi2 = __fdividef(AB, r2v.x + r2v.y + r2v.z + r2v.w + kGN);
            float Fi3 = __fdividef(AB, r3v.x + r3v.y + r3v.z + r3v.w + kGN);
            if (u == 0) {
                sF[i0 + 0  + rq] = Fi0; sF[i0 + 4  + rq] = Fi1;
                sF[i0 + 8  + rq] = Fi2; sF[i0 + 12 + rq] = Fi3;
            }
            if (!last) {
                S4.x += v0.x * Fi0 + v1.x * Fi1 + v2.x * Fi2 + v3.x * Fi3;
                S4.y += v0.y * Fi0 + v1.y * Fi1 + v2.y * Fi2 + v3.y * Fi3;
                S4.z += v0.z * Fi0 + v1.z * Fi1 + v2.z * Fi2 + v3.z * Fi3;
                S4.w += v0.w * Fi0 + v1.w * Fi1 + v2.w * Fi2 + v3.w * Fi3;
            }
            it ^= 1;
        }
        __syncthreads();
        if (!last) {
            *(float4*)&sSpart[rq][4 * u] = S4;
            __syncthreads();
            float Sj = sSpart[0][t] + sSpart[1][t] + sSpart[2][t] + sSpart[3][t];
            float newG = AB / (Sj + kappa * F_M);
            sG[t] = newG;
            // sumF
            float fv = warp_sum(sF[t]);
            if (lane == 0) sWred[warp] = fv;
            __syncthreads();
            float sumF = 0.f;
#pragma unroll
            for (int w = 0; w < 16; w++) sumF += sWred[w];
            G_N = AB_LAST / (kappa * (sumF + F_M));
            __syncthreads();
            // sumG
            float gv = warp_sum(newG);
            if (lane == 0) sWred[warp] = gv;
            __syncthreads();
            float sg = 0.f;
#pragma unroll
            for (int w = 0; w < 16; w++) sg += sWred[w];
            sumG_all = sg + G_N;
            __syncthreads();
        }
    }

    // store potentials (F^8, G^8 incl. bins)
    g_F[g * MP1 + t] = sF[t];
    g_G[g * MP1 + t] = sG[t];
    if (t == 0) { g_F[g * MP1 + 512] = F_M; g_G[g * MP1 + 512] = G_N; }
}

// ---------------- 4) output: pred[g][i][j] = F_i * K_ij * G_j (bins via kappa) ----------------
// grid (513, 128), block 512; one row per block -> fully coalesced reads/writes.
__global__ void output_kernel(const float* __restrict__ alpha_p, const float* __restrict__ eps_p,
                              float* __restrict__ out)
{
    int g = blockIdx.y;
    int i = blockIdx.x;             // 0..512
    int t = threadIdx.x;            // 0..511
    float lam = __expf(eps_p[0]) + 0.03f;
    float kappa = __expf(-alpha_p[0] / lam);
    float Fi = g_F[g * MP1 + i];
    float GN = g_G[g * MP1 + 512];
    float Gj = g_G[g * MP1 + t];
    float* orow = out + (size_t)g * MP1 * MP1 + (size_t)i * MP1;
    if (i < MDIM) {
        const float* Krow = g_K + (size_t)g * MDIM * NDIM + (size_t)i * NDIM;
        orow[t] = Fi * Krow[t] * Gj;
        if (t == 0) orow[512] = Fi * kappa * GN;
    } else {
        orow[t] = Fi * kappa * Gj;          // Fi == F_M here
        if (t == 0) orow[512] = Fi * kappa * GN;
    }
}

// ---------------- launch ----------------
extern "C" void kernel_launch(void* const* d_in, const int* in_sizes, int n_in,
                              void* d_out, int out_size) {
    const float* det   = (const float*)d_in[0];   // [G, N, D]
    const float* tra   = (const float*)d_in[1];   // [G, M, D]
    const float* alpha = (const float*)d_in[2];   // [1]
    const float* eps   = (const float*)d_in[3];   // [1]
    float* out = (float*)d_out;                   // [G, M+1, N+1]

    norm_kernel<<<dim3(8192, 2), 256>>>(tra, det);
    gemm_kernel<<<dim3(4, 4, 128), 256>>>(det, tra, alpha, eps);
    sinkhorn_kernel<<<128, 512>>>(alpha, eps);
    output_kernel<<<dim3(513, 128), 512>>>(alpha, eps, out);
}